// round 1
// baseline (speedup 1.0000x reference)
#include <cuda_runtime.h>
#include <cstdint>
#include <cstddef>

// Problem constants (fixed by the reference setup)
#define Bb   2
#define Ss   2048
#define Hh   32
#define KVHh 8
#define Dd   128
#define QT   128   // query rows per CTA
#define KT   64    // kv tokens per tile
#define QLD  132   // smem leading dims (bank-conflict-free padding)
#define KLD  132
#define VLD  136

static constexpr int SMEM_FLOATS = QT * QLD + KT * KLD + KT * VLD;
static constexpr int SMEM_BYTES  = SMEM_FLOATS * 4;  // 136,192 B

__device__ __forceinline__ uint32_t f2tf(float x) {
    uint32_t r;
    asm("cvt.rna.tf32.f32 %0, %1;" : "=r"(r) : "f"(x));
    return r;
}
__device__ __forceinline__ float f2tff(float x) { return __uint_as_float(f2tf(x)); }

__device__ __forceinline__ void mma8(float c[4], const uint32_t a[4], const uint32_t b[2]) {
    asm volatile(
        "mma.sync.aligned.m16n8k8.row.col.f32.tf32.tf32.f32 "
        "{%0,%1,%2,%3}, {%4,%5,%6,%7}, {%8,%9}, {%0,%1,%2,%3};"
        : "+f"(c[0]), "+f"(c[1]), "+f"(c[2]), "+f"(c[3])
        : "r"(a[0]), "r"(a[1]), "r"(a[2]), "r"(a[3]), "r"(b[0]), "r"(b[1]));
}

__global__ void __launch_bounds__(256, 1)
attn_kernel(const float* __restrict__ xq, const float* __restrict__ xk,
            const float* __restrict__ xv, float* __restrict__ out)
{
    extern __shared__ float sm[];
    float* Qs = sm;                    // [QT][QLD]
    float* Ks = sm + QT * QLD;         // [KT][KLD]
    float* Vs = Ks + KT * KLD;         // [KT][VLD]

    const int qt  = blockIdx.x;        // 0..15
    const int h   = blockIdx.y;        // 0..31
    const int bb  = blockIdx.z;        // 0..1
    const int kh  = h >> 2;            // G = 4
    const int tid = threadIdx.x;
    const int w   = tid >> 5;          // warp 0..7, owns rows [16w,16w+16)
    const int l   = tid & 31;
    const int lq  = l >> 2;            // 0..7
    const int lg  = l & 3;             // 0..3

    // fold softmax scale and log2(e) into Q so we can use exp2f
    const float qscale = 0.08838834764831845f * 1.4426950408889634f;

    // ---- stage Q tile [128 x 128] into smem as TF32 ----
    {
        const float4* qg = (const float4*)(xq + (((size_t)bb * Ss + (size_t)qt * QT) * Hh + h) * Dd);
        const size_t rowstride4 = (size_t)Hh * Dd / 4;  // 1024 float4 per q-row
        #pragma unroll
        for (int i = 0; i < 16; i++) {
            int idx = tid + i * 256;     // 0..4095
            int row = idx >> 5;          // 32 float4 per tile row
            int c4  = idx & 31;
            float4 v = qg[(size_t)row * rowstride4 + c4];
            float* qd = Qs + row * QLD + c4 * 4;
            qd[0] = f2tff(v.x * qscale);
            qd[1] = f2tff(v.y * qscale);
            qd[2] = f2tff(v.z * qscale);
            qd[3] = f2tff(v.w * qscale);
        }
    }

    float o[16][4];
    #pragma unroll
    for (int i = 0; i < 16; i++) { o[i][0] = 0.f; o[i][1] = 0.f; o[i][2] = 0.f; o[i][3] = 0.f; }

    const int qrow0 = qt * QT + w * 16 + lq;   // rows for C-fragment regs {0,1}
    const int qrow1 = qrow0 + 8;               // rows for regs {2,3}
    float m0 = -1e30f, m1 = -1e30f, l0 = 0.f, l1 = 0.f;

    const int nkt = 2 * qt + 2;                // causal tile count

    for (int kt = 0; kt < nkt; ++kt) {
        __syncthreads();   // previous iteration's smem reads complete

        // ---- load K,V tiles [64 x 128] into smem as TF32 ----
        {
            const size_t base = (((size_t)bb * Ss + (size_t)kt * KT) * KVHh + kh) * Dd;
            const float4* kg = (const float4*)(xk + base);
            const float4* vg = (const float4*)(xv + base);
            const size_t rowstride4 = (size_t)KVHh * Dd / 4;  // 256 float4 per token
            #pragma unroll
            for (int i = 0; i < 8; i++) {
                int idx = tid + i * 256;   // 0..2047
                int row = idx >> 5;
                int c4  = idx & 31;
                size_t g = (size_t)row * rowstride4 + c4;
                float4 kv = kg[g];
                float* kd = Ks + row * KLD + c4 * 4;
                kd[0] = f2tff(kv.x); kd[1] = f2tff(kv.y);
                kd[2] = f2tff(kv.z); kd[3] = f2tff(kv.w);
                float4 vv = vg[g];
                float* vd = Vs + row * VLD + c4 * 4;
                vd[0] = f2tff(vv.x); vd[1] = f2tff(vv.y);
                vd[2] = f2tff(vv.z); vd[3] = f2tff(vv.w);
            }
        }
        __syncthreads();

        // ---- S = Q * K^T  (16x64 per warp, over D=128) ----
        float s[8][4];
        #pragma unroll
        for (int nt = 0; nt < 8; nt++) { s[nt][0] = 0.f; s[nt][1] = 0.f; s[nt][2] = 0.f; s[nt][3] = 0.f; }

        #pragma unroll
        for (int ks = 0; ks < 16; ++ks) {
            uint32_t af[4];
            const float* qp = Qs + (w * 16 + lq) * QLD + ks * 8 + lg;
            af[0] = __float_as_uint(qp[0]);
            af[1] = __float_as_uint(qp[8 * QLD]);
            af[2] = __float_as_uint(qp[4]);
            af[3] = __float_as_uint(qp[8 * QLD + 4]);
            #pragma unroll
            for (int nt = 0; nt < 8; ++nt) {
                uint32_t bf[2];
                const float* kp = Ks + (nt * 8 + lq) * KLD + ks * 8 + lg;
                bf[0] = __float_as_uint(kp[0]);
                bf[1] = __float_as_uint(kp[4]);
                mma8(s[nt], af, bf);
            }
        }

        // ---- causal mask (only last two tiles need it) ----
        const int kb = kt * KT;
        if (kt >= nkt - 2) {
            #pragma unroll
            for (int nt = 0; nt < 8; nt++) {
                int tok = kb + nt * 8 + 2 * lg;
                if (tok     > qrow0) s[nt][0] = -1e30f;
                if (tok + 1 > qrow0) s[nt][1] = -1e30f;
                if (tok     > qrow1) s[nt][2] = -1e30f;
                if (tok + 1 > qrow1) s[nt][3] = -1e30f;
            }
        }

        // ---- online softmax (base-2 domain) ----
        float rm0 = -1e30f, rm1 = -1e30f;
        #pragma unroll
        for (int nt = 0; nt < 8; nt++) {
            rm0 = fmaxf(rm0, fmaxf(s[nt][0], s[nt][1]));
            rm1 = fmaxf(rm1, fmaxf(s[nt][2], s[nt][3]));
        }
        rm0 = fmaxf(rm0, __shfl_xor_sync(0xffffffffu, rm0, 1));
        rm0 = fmaxf(rm0, __shfl_xor_sync(0xffffffffu, rm0, 2));
        rm1 = fmaxf(rm1, __shfl_xor_sync(0xffffffffu, rm1, 1));
        rm1 = fmaxf(rm1, __shfl_xor_sync(0xffffffffu, rm1, 2));

        float mn0 = fmaxf(m0, rm0), mn1 = fmaxf(m1, rm1);
        float a0 = exp2f(m0 - mn0), a1 = exp2f(m1 - mn1);
        float rs0 = 0.f, rs1 = 0.f;
        #pragma unroll
        for (int nt = 0; nt < 8; nt++) {
            s[nt][0] = exp2f(s[nt][0] - mn0);
            s[nt][1] = exp2f(s[nt][1] - mn0);
            s[nt][2] = exp2f(s[nt][2] - mn1);
            s[nt][3] = exp2f(s[nt][3] - mn1);
            rs0 += s[nt][0] + s[nt][1];
            rs1 += s[nt][2] + s[nt][3];
        }
        rs0 += __shfl_xor_sync(0xffffffffu, rs0, 1);
        rs0 += __shfl_xor_sync(0xffffffffu, rs0, 2);
        rs1 += __shfl_xor_sync(0xffffffffu, rs1, 1);
        rs1 += __shfl_xor_sync(0xffffffffu, rs1, 2);
        l0 = l0 * a0 + rs0;
        l1 = l1 * a1 + rs1;
        m0 = mn0; m1 = mn1;

        #pragma unroll
        for (int i = 0; i < 16; i++) {
            o[i][0] *= a0; o[i][1] *= a0;
            o[i][2] *= a1; o[i][3] *= a1;
        }

        // ---- O += P * V ----
        // P A-frags built from S C-frags via intra-quad shuffles.
        const int src  = (l & 28) | (lg >> 1);
        const int src2 = src + 2;
        const bool odd = (lg & 1);
        #pragma unroll
        for (int ksp = 0; ksp < 8; ++ksp) {
            float v00 = __shfl_sync(0xffffffffu, s[ksp][0], src);
            float v01 = __shfl_sync(0xffffffffu, s[ksp][1], src);
            float v10 = __shfl_sync(0xffffffffu, s[ksp][2], src);
            float v11 = __shfl_sync(0xffffffffu, s[ksp][3], src);
            float w00 = __shfl_sync(0xffffffffu, s[ksp][0], src2);
            float w01 = __shfl_sync(0xffffffffu, s[ksp][1], src2);
            float w10 = __shfl_sync(0xffffffffu, s[ksp][2], src2);
            float w11 = __shfl_sync(0xffffffffu, s[ksp][3], src2);
            uint32_t af[4];
            af[0] = f2tf(odd ? v01 : v00);   // row r0, k-col lg
            af[1] = f2tf(odd ? v11 : v10);   // row r1, k-col lg
            af[2] = f2tf(odd ? w01 : w00);   // row r0, k-col lg+4
            af[3] = f2tf(odd ? w11 : w10);   // row r1, k-col lg+4
            #pragma unroll
            for (int d8 = 0; d8 < 16; ++d8) {
                uint32_t bf[2];
                const float* vp = Vs + (ksp * 8 + lg) * VLD + d8 * 8 + lq;
                bf[0] = __float_as_uint(vp[0]);
                bf[1] = __float_as_uint(vp[4 * VLD]);
                mma8(o[d8], af, bf);
            }
        }
    }

    // ---- epilogue: normalize and write out [B,S,H*D] ----
    const float inv0 = 1.f / l0, inv1 = 1.f / l1;
    float* op0 = out + (((size_t)bb * Ss + qrow0) * Hh + h) * Dd;
    float* op1 = out + (((size_t)bb * Ss + qrow1) * Hh + h) * Dd;
    #pragma unroll
    for (int d8 = 0; d8 < 16; ++d8) {
        int c = d8 * 8 + 2 * lg;
        *(float2*)(op0 + c) = make_float2(o[d8][0] * inv0, o[d8][1] * inv0);
        *(float2*)(op1 + c) = make_float2(o[d8][2] * inv1, o[d8][3] * inv1);
    }
}

// ---- KV cache: copy buffer then scatter new K/V ----
__global__ void kvcopy_kernel(const float4* __restrict__ src, float4* __restrict__ dst, int n4) {
    int i = blockIdx.x * blockDim.x + threadIdx.x;
    if (i < n4) dst[i] = src[i];
}

__global__ void kvscatter_kernel(const float* __restrict__ xk, const float* __restrict__ xv,
                                 const int* __restrict__ sel, float* __restrict__ dst) {
    int t = blockIdx.x;                 // flat token 0..B*S-1
    int slot = sel[t];
    const float4* k4 = (const float4*)(xk + (size_t)t * KVHh * Dd);
    const float4* v4 = (const float4*)(xv + (size_t)t * KVHh * Dd);
    float4* d4 = (float4*)(dst + (size_t)slot * 2 * KVHh * Dd);
    int tid = threadIdx.x;              // 256 threads; 256 float4 per K row-block
    d4[tid]       = k4[tid];
    d4[256 + tid] = v4[tid];
}

extern "C" void kernel_launch(void* const* d_in, const int* in_sizes, int n_in,
                              void* d_out, int out_size) {
    const float* xq  = (const float*)d_in[0];
    const float* xk  = (const float*)d_in[1];
    const float* xv  = (const float*)d_in[2];
    const float* kvb = (const float*)d_in[3];
    const int*   sel = (const int*)d_in[4];

    float* out = (float*)d_out;
    const int attn_elems = Bb * Ss * Hh * Dd;      // 16,777,216
    const int kv_elems   = in_sizes[3];            // 16,777,216

    cudaFuncSetAttribute(attn_kernel, cudaFuncAttributeMaxDynamicSharedMemorySize, SMEM_BYTES);

    dim3 grid(Ss / QT, Hh, Bb);
    attn_kernel<<<grid, 256, SMEM_BYTES>>>(xq, xk, xv, out);

    if (out_size >= attn_elems + kv_elems) {
        float* kvout = out + attn_elems;
        int n4 = kv_elems / 4;
        kvcopy_kernel<<<(n4 + 255) / 256, 256>>>((const float4*)kvb, (float4*)kvout, n4);
        kvscatter_kernel<<<Bb * Ss, 256>>>(xk, xv, sel, kvout);
    }
}